// round 1
// baseline (speedup 1.0000x reference)
#include <cuda_runtime.h>
#include <cstdint>

// ---------------------------------------------------------------------------
// Problem constants (fixed by the reference)
// ---------------------------------------------------------------------------
#define N_NODES_MAX   10000
#define NUM_FEAT      384
#define F_HEAD        128
#define NHEADS        3
#define SPH_DIM       15
#define INV_SQRT_FH   0.08838834764831845f   // 1/sqrt(128)

// Scratch for projected q/k (device globals: no allocation allowed)
__device__ float g_q[N_NODES_MAX * NUM_FEAT];
__device__ float g_k[N_NODES_MAX * NUM_FEAT];

// ---------------------------------------------------------------------------
// Zero-init kernel (d_out is poisoned to 0xAA)
// ---------------------------------------------------------------------------
__global__ void zero_kernel(float* out, int n) {
    int i = blockIdx.x * blockDim.x + threadIdx.x;
    if (i < n) out[i] = 0.0f;
}

// ---------------------------------------------------------------------------
// Projection: q[n,h,g] = sum_f x[n, h*128+f] * Wq[h, g, f]   (same for k)
// Block: 256 threads (16x16), C-tile = 64 rows x 128 cols, K chunked by 16.
// blockIdx.x = row tile, blockIdx.y = head, blockIdx.z = {0:q, 1:k}
// 1/sqrt(128) is folded into q.
// ---------------------------------------------------------------------------
__global__ __launch_bounds__(256) void proj_kernel(
    const float* __restrict__ x,
    const float* __restrict__ Wq,
    const float* __restrict__ Wk,
    int n_nodes)
{
    const int h    = blockIdx.y;
    const int row0 = blockIdx.x * 64;
    const bool is_k = (blockIdx.z != 0);
    const float* __restrict__ W = (is_k ? Wk : Wq) + h * F_HEAD * F_HEAD;
    float* __restrict__ out = is_k ? g_k : g_q;
    const float scale = is_k ? 1.0f : INV_SQRT_FH;

    __shared__ float Xs[64][17];    // [row][kk], padded
    __shared__ float Ws[16][132];   // [kk][g],   padded

    const int tx = threadIdx.x & 15;   // column group (8 cols each)
    const int ty = threadIdx.x >> 4;   // row group    (4 rows each)

    float acc[4][8];
    #pragma unroll
    for (int r = 0; r < 4; r++)
        #pragma unroll
        for (int c = 0; c < 8; c++) acc[r][c] = 0.0f;

    for (int k0 = 0; k0 < F_HEAD; k0 += 16) {
        // Stage X tile: 64 x 16
        #pragma unroll
        for (int i = threadIdx.x; i < 64 * 16; i += 256) {
            int r = i >> 4, kk = i & 15;
            int row = row0 + r;
            Xs[r][kk] = (row < n_nodes) ? x[row * NUM_FEAT + h * F_HEAD + k0 + kk]
                                        : 0.0f;
        }
        // Stage W tile transposed: Ws[kk][g], 128 x 16
        #pragma unroll
        for (int i = threadIdx.x; i < 128 * 16; i += 256) {
            int g = i >> 4, kk = i & 15;
            Ws[kk][g] = W[g * F_HEAD + k0 + kk];
        }
        __syncthreads();

        #pragma unroll
        for (int kk = 0; kk < 16; kk++) {
            float xr[4];
            #pragma unroll
            for (int r = 0; r < 4; r++) xr[r] = Xs[ty * 4 + r][kk];
            float wg[8];
            #pragma unroll
            for (int c = 0; c < 8; c++) wg[c] = Ws[kk][tx * 8 + c];
            #pragma unroll
            for (int r = 0; r < 4; r++)
                #pragma unroll
                for (int c = 0; c < 8; c++)
                    acc[r][c] += xr[r] * wg[c];
        }
        __syncthreads();
    }

    #pragma unroll
    for (int r = 0; r < 4; r++) {
        int row = row0 + ty * 4 + r;
        if (row < n_nodes) {
            float* o = out + (size_t)row * NUM_FEAT + h * F_HEAD + tx * 8;
            #pragma unroll
            for (int c = 0; c < 8; c++) o[c] = acc[r][c] * scale;
        }
    }
}

// ---------------------------------------------------------------------------
// Edge kernel: one warp per edge.
//   alpha_h = dot(q[i,h,:], w[e,h,:] * k[j,h,:])        (q pre-scaled)
//   alpha_h *= (phi_r[e] + phi_chi[e])
//   out[i, s] += alpha_{head(s)} * sph[e, s]            (atomic, s in [0,15))
// float4 loads: f = (lane + jj*32)*4, so jj == head exactly.
// ---------------------------------------------------------------------------
__global__ __launch_bounds__(256) void edge_kernel(
    const float* __restrict__ w_ij,
    const float* __restrict__ sph,
    const int*   __restrict__ idx_i,
    const int*   __restrict__ idx_j,
    const float* __restrict__ phi_r,
    const float* __restrict__ phi_chi,
    float* __restrict__ out,
    int n_pairs)
{
    const int e    = (blockIdx.x * blockDim.x + threadIdx.x) >> 5;
    const int lane = threadIdx.x & 31;
    if (e >= n_pairs) return;

    const int ni = idx_i[e];
    const int nj = idx_j[e];

    const float4* __restrict__ q4 = (const float4*)(g_q + (size_t)ni * NUM_FEAT);
    const float4* __restrict__ k4 = (const float4*)(g_k + (size_t)nj * NUM_FEAT);
    const float4* __restrict__ w4 = (const float4*)(w_ij + (size_t)e * NUM_FEAT);

    float a[NHEADS];
    #pragma unroll
    for (int hh = 0; hh < NHEADS; hh++) {
        const int idx = lane + hh * 32;           // float4 index; head == hh
        const float4 qv = q4[idx];
        const float4 wv = w4[idx];
        const float4 kv = k4[idx];
        a[hh] = qv.x * wv.x * kv.x
              + qv.y * wv.y * kv.y
              + qv.z * wv.z * kv.z
              + qv.w * wv.w * kv.w;
    }

    // Warp reduction (all 3 heads together)
    #pragma unroll
    for (int off = 16; off > 0; off >>= 1) {
        #pragma unroll
        for (int hh = 0; hh < NHEADS; hh++)
            a[hh] += __shfl_xor_sync(0xFFFFFFFFu, a[hh], off);
    }

    const float cut = phi_r[e] + phi_chi[e];

    if (lane < SPH_DIM) {
        const float alpha = (lane < 3 ? a[0] : (lane < 8 ? a[1] : a[2])) * cut;
        atomicAdd(&out[(size_t)ni * SPH_DIM + lane],
                  alpha * sph[(size_t)e * SPH_DIM + lane]);
    }
}

// ---------------------------------------------------------------------------
// Launch
// Inputs (metadata order):
//  0: chi (unused)  1: sph_ij  2: x  3: w_ij  4: idx_i  5: phi_r_cut
//  6: phi_chi_cut   7: idx_j   8: Wq 9: Wk
// ---------------------------------------------------------------------------
extern "C" void kernel_launch(void* const* d_in, const int* in_sizes, int n_in,
                              void* d_out, int out_size)
{
    const float* sph     = (const float*)d_in[1];
    const float* x       = (const float*)d_in[2];
    const float* w_ij    = (const float*)d_in[3];
    const int*   idx_i   = (const int*)  d_in[4];
    const float* phi_r   = (const float*)d_in[5];
    const float* phi_chi = (const float*)d_in[6];
    const int*   idx_j   = (const int*)  d_in[7];
    const float* Wq      = (const float*)d_in[8];
    const float* Wk      = (const float*)d_in[9];
    float* out = (float*)d_out;

    const int n_nodes = in_sizes[2] / NUM_FEAT;
    const int n_pairs = in_sizes[4];

    // 1) zero output
    zero_kernel<<<(out_size + 255) / 256, 256>>>(out, out_size);

    // 2) projections q, k
    dim3 pgrid((n_nodes + 63) / 64, NHEADS, 2);
    proj_kernel<<<pgrid, 256>>>(x, Wq, Wk, n_nodes);

    // 3) edge attention + scatter
    const int warps_per_block = 256 / 32;
    const int eblocks = (n_pairs + warps_per_block - 1) / warps_per_block;
    edge_kernel<<<eblocks, 256>>>(w_ij, sph, idx_i, idx_j, phi_r, phi_chi,
                                  out, n_pairs);
}

// round 2
// speedup vs baseline: 1.1178x; 1.1178x over previous
#include <cuda_runtime.h>
#include <cstdint>

#define N_NODES_MAX   10000
#define NUM_FEAT      384
#define F_HEAD        128
#define NHEADS        3
#define SPH_DIM       15
#define INV_SQRT_FH   0.08838834764831845f   // 1/sqrt(128)

// Scratch for projected q/k (device globals: no allocation allowed)
__device__ float g_q[N_NODES_MAX * NUM_FEAT];
__device__ float g_k[N_NODES_MAX * NUM_FEAT];

// ---------------------------------------------------------------------------
// Packed fp32x2 helpers (sm_100+: FFMA2 via PTX fma.rn.f32x2)
// ---------------------------------------------------------------------------
__device__ __forceinline__ unsigned long long pack2_dup(float x) {
    unsigned long long r;
    asm("mov.b64 %0, {%1, %1};" : "=l"(r) : "f"(x));
    return r;
}
__device__ __forceinline__ void fma2(unsigned long long& acc,
                                     unsigned long long a,
                                     unsigned long long b) {
    asm("fma.rn.f32x2 %0, %1, %2, %0;" : "+l"(acc) : "l"(a), "l"(b));
}
__device__ __forceinline__ void unpack2(float& lo, float& hi, unsigned long long v) {
    asm("mov.b64 {%0, %1}, %2;" : "=f"(lo), "=f"(hi) : "l"(v));
}

// ---------------------------------------------------------------------------
// Zero-init kernel (d_out is poisoned to 0xAA)
// ---------------------------------------------------------------------------
__global__ void zero_kernel(float* out, int n) {
    int i = blockIdx.x * blockDim.x + threadIdx.x;
    if (i < n) out[i] = 0.0f;
}

// ---------------------------------------------------------------------------
// Projection: q[n,h,g] = sum_f x[n, h*128+f] * Wq[h, g, f]   (same for k)
// Block: 256 threads (16x16), C-tile = 64 rows x 128 cols, K chunked by 16.
// blockIdx.x = row tile, blockIdx.y = head, blockIdx.z = {0:q, 1:k}
// 1/sqrt(128) folded into q. Inner loop uses packed FFMA2.
// ---------------------------------------------------------------------------
__global__ __launch_bounds__(256) void proj_kernel(
    const float* __restrict__ x,
    const float* __restrict__ Wq,
    const float* __restrict__ Wk,
    int n_nodes)
{
    const int h    = blockIdx.y;
    const int row0 = blockIdx.x * 64;
    const bool is_k = (blockIdx.z != 0);
    const float* __restrict__ W = (is_k ? Wk : Wq) + h * F_HEAD * F_HEAD;
    float* __restrict__ out = is_k ? g_k : g_q;
    const float scale = is_k ? 1.0f : INV_SQRT_FH;

    // Xs transposed: [kk][row], row-pad 68 (272B, 16B-aligned rows)
    __shared__ float Xs[16][68];
    // Ws: [kk][g], row-pad 132 (528B, 16B-aligned rows)
    __shared__ float Ws[16][132];

    const int tx = threadIdx.x & 15;   // column group (8 cols each)
    const int ty = threadIdx.x >> 4;   // row group    (4 rows each)

    // acc2[r][cc] = packed pair (col 2cc, 2cc+1) for row r
    unsigned long long acc2[4][4];
    #pragma unroll
    for (int r = 0; r < 4; r++)
        #pragma unroll
        for (int c = 0; c < 4; c++) acc2[r][c] = 0ull;

    for (int k0 = 0; k0 < F_HEAD; k0 += 16) {
        // Stage X tile (transposed): Xs[kk][r]
        #pragma unroll
        for (int i = threadIdx.x; i < 64 * 16; i += 256) {
            int r = i >> 4, kk = i & 15;
            int row = row0 + r;
            Xs[kk][r] = (row < n_nodes)
                        ? x[row * NUM_FEAT + h * F_HEAD + k0 + kk] : 0.0f;
        }
        // Stage W tile transposed: Ws[kk][g]
        #pragma unroll
        for (int i = threadIdx.x; i < 128 * 16; i += 256) {
            int g = i >> 4, kk = i & 15;
            Ws[kk][g] = W[g * F_HEAD + k0 + kk];
        }
        __syncthreads();

        #pragma unroll
        for (int kk = 0; kk < 16; kk++) {
            // one LDS.128: 4 consecutive row-values for this thread
            const float4 xv = *(const float4*)&Xs[kk][ty * 4];
            // two LDS.128: 8 consecutive cols = 4 packed f32x2 pairs
            const ulonglong2 wA = *(const ulonglong2*)&Ws[kk][tx * 8];
            const ulonglong2 wB = *(const ulonglong2*)&Ws[kk][tx * 8 + 4];

            unsigned long long xp[4];
            xp[0] = pack2_dup(xv.x);
            xp[1] = pack2_dup(xv.y);
            xp[2] = pack2_dup(xv.z);
            xp[3] = pack2_dup(xv.w);

            #pragma unroll
            for (int r = 0; r < 4; r++) {
                fma2(acc2[r][0], xp[r], wA.x);
                fma2(acc2[r][1], xp[r], wA.y);
                fma2(acc2[r][2], xp[r], wB.x);
                fma2(acc2[r][3], xp[r], wB.y);
            }
        }
        __syncthreads();
    }

    #pragma unroll
    for (int r = 0; r < 4; r++) {
        int row = row0 + ty * 4 + r;
        if (row < n_nodes) {
            float* o = out + (size_t)row * NUM_FEAT + h * F_HEAD + tx * 8;
            #pragma unroll
            for (int cc = 0; cc < 4; cc++) {
                float lo, hi;
                unpack2(lo, hi, acc2[r][cc]);
                o[cc * 2 + 0] = lo * scale;
                o[cc * 2 + 1] = hi * scale;
            }
        }
    }
}

// ---------------------------------------------------------------------------
// Edge kernel: one warp per edge.
//   alpha_h = dot(q[i,h,:], w[e,h,:] * k[j,h,:])        (q pre-scaled)
//   alpha_h *= (phi_r[e] + phi_chi[e])
//   out[i, s] += alpha_{head(s)} * sph[e, s]            (atomic)
// float4 loads: f4-index = lane + hh*32, so hh == head exactly.
// Streaming hints on the one-shot w_ij/sph streams.
// ---------------------------------------------------------------------------
__global__ __launch_bounds__(256) void edge_kernel(
    const float* __restrict__ w_ij,
    const float* __restrict__ sph,
    const int*   __restrict__ idx_i,
    const int*   __restrict__ idx_j,
    const float* __restrict__ phi_r,
    const float* __restrict__ phi_chi,
    float* __restrict__ out,
    int n_pairs)
{
    const int e    = (blockIdx.x * blockDim.x + threadIdx.x) >> 5;
    const int lane = threadIdx.x & 31;
    if (e >= n_pairs) return;

    const int ni = idx_i[e];
    const int nj = idx_j[e];

    const float4* __restrict__ q4 = (const float4*)(g_q + (size_t)ni * NUM_FEAT);
    const float4* __restrict__ k4 = (const float4*)(g_k + (size_t)nj * NUM_FEAT);
    const float4* __restrict__ w4 = (const float4*)(w_ij + (size_t)e * NUM_FEAT);

    float a[NHEADS];
    #pragma unroll
    for (int hh = 0; hh < NHEADS; hh++) {
        const int idx = lane + hh * 32;
        const float4 qv = __ldg(&q4[idx]);
        const float4 wv = __ldcs(&w4[idx]);     // streaming: read-once
        const float4 kv = __ldg(&k4[idx]);
        a[hh] = qv.x * wv.x * kv.x
              + qv.y * wv.y * kv.y
              + qv.z * wv.z * kv.z
              + qv.w * wv.w * kv.w;
    }

    #pragma unroll
    for (int off = 16; off > 0; off >>= 1) {
        #pragma unroll
        for (int hh = 0; hh < NHEADS; hh++)
            a[hh] += __shfl_xor_sync(0xFFFFFFFFu, a[hh], off);
    }

    const float cut = phi_r[e] + phi_chi[e];

    if (lane < SPH_DIM) {
        const float alpha = (lane < 3 ? a[0] : (lane < 8 ? a[1] : a[2])) * cut;
        atomicAdd(&out[(size_t)ni * SPH_DIM + lane],
                  alpha * __ldcs(&sph[(size_t)e * SPH_DIM + lane]));
    }
}

// ---------------------------------------------------------------------------
// Launch. Inputs (metadata order):
//  0: chi (unused)  1: sph_ij  2: x  3: w_ij  4: idx_i  5: phi_r_cut
//  6: phi_chi_cut   7: idx_j   8: Wq 9: Wk
// ---------------------------------------------------------------------------
extern "C" void kernel_launch(void* const* d_in, const int* in_sizes, int n_in,
                              void* d_out, int out_size)
{
    const float* sph     = (const float*)d_in[1];
    const float* x       = (const float*)d_in[2];
    const float* w_ij    = (const float*)d_in[3];
    const int*   idx_i   = (const int*)  d_in[4];
    const float* phi_r   = (const float*)d_in[5];
    const float* phi_chi = (const float*)d_in[6];
    const int*   idx_j   = (const int*)  d_in[7];
    const float* Wq      = (const float*)d_in[8];
    const float* Wk      = (const float*)d_in[9];
    float* out = (float*)d_out;

    const int n_nodes = in_sizes[2] / NUM_FEAT;
    const int n_pairs = in_sizes[4];

    zero_kernel<<<(out_size + 255) / 256, 256>>>(out, out_size);

    dim3 pgrid((n_nodes + 63) / 64, NHEADS, 2);
    proj_kernel<<<pgrid, 256>>>(x, Wq, Wk, n_nodes);

    const int warps_per_block = 256 / 32;
    const int eblocks = (n_pairs + warps_per_block - 1) / warps_per_block;
    edge_kernel<<<eblocks, 256>>>(w_ij, sph, idx_i, idx_j, phi_r, phi_chi,
                                  out, n_pairs);
}

// round 3
// speedup vs baseline: 1.6973x; 1.5184x over previous
#include <cuda_runtime.h>
#include <cuda_fp16.h>
#include <cstdint>

#define N_NODES_MAX   10000
#define NUM_FEAT      384
#define F_HEAD        128
#define NHEADS        3
#define SPH_DIM       15
#define INV_SQRT_FH   0.08838834764831845f   // 1/sqrt(128)

// Scratch: projected q/k in fp16 (device globals: no allocation allowed)
__device__ __half g_qh[N_NODES_MAX * NUM_FEAT];
__device__ __half g_kh[N_NODES_MAX * NUM_FEAT];

struct __align__(8) Half4 { __half2 a, b; };

// ---------------------------------------------------------------------------
// Packed fp32x2 helpers (sm_100+: FFMA2 via PTX fma.rn.f32x2)
// ---------------------------------------------------------------------------
__device__ __forceinline__ unsigned long long pack2_dup(float x) {
    unsigned long long r;
    asm("mov.b64 %0, {%1, %1};" : "=l"(r) : "f"(x));
    return r;
}
__device__ __forceinline__ void fma2(unsigned long long& acc,
                                     unsigned long long a,
                                     unsigned long long b) {
    asm("fma.rn.f32x2 %0, %1, %2, %0;" : "+l"(acc) : "l"(a), "l"(b));
}
__device__ __forceinline__ void unpack2(float& lo, float& hi, unsigned long long v) {
    asm("mov.b64 {%0, %1}, %2;" : "=f"(lo), "=f"(hi) : "l"(v));
}

// ---------------------------------------------------------------------------
// Projection: q[n,h,g] = (1/sqrt(128)) * sum_f x[n,h*128+f] * Wq[h,g,f]
//             k[n,h,g] =                 sum_f x[n,h*128+f] * Wk[h,g,f]
// Output stored as fp16. Also zero-inits `out` (blocks y==0,z==0).
// Block: 256 threads (tx 0..15 = 8 cols each; ty 0..15 = 8 rows each)
// C-tile: 128 rows x 128 cols. K chunked by 16. FFMA2 inner loop.
// ---------------------------------------------------------------------------
__global__ __launch_bounds__(256) void proj_kernel(
    const float* __restrict__ x,
    const float* __restrict__ Wq,
    const float* __restrict__ Wk,
    float* __restrict__ out, int out_n,
    int n_nodes)
{
    // Fold the output zero-init into this kernel (out poisoned to 0xAA).
    if (blockIdx.y == 0 && blockIdx.z == 0) {
        for (int i = blockIdx.x * 256 + threadIdx.x; i < out_n;
             i += gridDim.x * 256)
            out[i] = 0.0f;
    }

    const int h    = blockIdx.y;
    const int row0 = blockIdx.x * 128;
    const bool is_k = (blockIdx.z != 0);
    const float* __restrict__ W = (is_k ? Wk : Wq) + h * F_HEAD * F_HEAD;
    __half* __restrict__ o_base = is_k ? g_kh : g_qh;
    const float scale = is_k ? 1.0f : INV_SQRT_FH;

    __shared__ float Xs[16][132];   // [kk][row]  (132: 16B-mult rows, 2-way bank)
    __shared__ float Ws[16][132];   // [kk][col]

    const int tx = threadIdx.x & 15;   // col group (8 cols)
    const int ty = threadIdx.x >> 4;   // row group (8 rows)

    unsigned long long acc2[8][4];     // [row][col-pair]
    #pragma unroll
    for (int r = 0; r < 8; r++)
        #pragma unroll
        for (int c = 0; c < 4; c++) acc2[r][c] = 0ull;

    for (int k0 = 0; k0 < F_HEAD; k0 += 16) {
        // Stage X tile transposed: Xs[kk][r], 128 x 16
        #pragma unroll
        for (int i = threadIdx.x; i < 128 * 16; i += 256) {
            int r = i >> 4, kk = i & 15;
            int row = row0 + r;
            Xs[kk][r] = (row < n_nodes)
                        ? x[row * NUM_FEAT + h * F_HEAD + k0 + kk] : 0.0f;
        }
        // Stage W tile transposed: Ws[kk][g], 128 x 16
        #pragma unroll
        for (int i = threadIdx.x; i < 128 * 16; i += 256) {
            int g = i >> 4, kk = i & 15;
            Ws[kk][g] = W[g * F_HEAD + k0 + kk];
        }
        __syncthreads();

        #pragma unroll
        for (int kk = 0; kk < 16; kk++) {
            const float4 xlo = *(const float4*)&Xs[kk][ty * 8];
            const float4 xhi = *(const float4*)&Xs[kk][ty * 8 + 4];
            const ulonglong2 wA = *(const ulonglong2*)&Ws[kk][tx * 8];
            const ulonglong2 wB = *(const ulonglong2*)&Ws[kk][tx * 8 + 4];

            unsigned long long xp[8];
            xp[0] = pack2_dup(xlo.x);  xp[1] = pack2_dup(xlo.y);
            xp[2] = pack2_dup(xlo.z);  xp[3] = pack2_dup(xlo.w);
            xp[4] = pack2_dup(xhi.x);  xp[5] = pack2_dup(xhi.y);
            xp[6] = pack2_dup(xhi.z);  xp[7] = pack2_dup(xhi.w);

            #pragma unroll
            for (int r = 0; r < 8; r++) {
                fma2(acc2[r][0], xp[r], wA.x);
                fma2(acc2[r][1], xp[r], wA.y);
                fma2(acc2[r][2], xp[r], wB.x);
                fma2(acc2[r][3], xp[r], wB.y);
            }
        }
        __syncthreads();
    }

    // Store as fp16: per row, 4 half2 = one uint4 (16B aligned)
    #pragma unroll
    for (int r = 0; r < 8; r++) {
        int row = row0 + ty * 8 + r;
        if (row < n_nodes) {
            __half2 h4[4];
            #pragma unroll
            for (int cc = 0; cc < 4; cc++) {
                float lo, hi;
                unpack2(lo, hi, acc2[r][cc]);
                h4[cc] = __floats2half2_rn(lo * scale, hi * scale);
            }
            *(uint4*)(o_base + (size_t)row * NUM_FEAT + h * F_HEAD + tx * 8)
                = *(const uint4*)h4;
        }
    }
}

// ---------------------------------------------------------------------------
// Edge kernel: one warp per edge.
//   alpha_h = dot(q[i,h,:], w[e,h,:] * k[j,h,:])        (q pre-scaled)
//   alpha_h *= (phi_r[e] + phi_chi[e])
//   out[i, s] += alpha_{head(s)} * sph[e, s]            (atomic)
// q/k gathered as fp16 (half the L2 gather traffic), fp32 accumulate.
// Feature index per (lane, head): 4 feats at 4*(lane + hh*32) = lane*4 + hh*128.
// ---------------------------------------------------------------------------
__global__ __launch_bounds__(256) void edge_kernel(
    const float* __restrict__ w_ij,
    const float* __restrict__ sph,
    const int*   __restrict__ idx_i,
    const int*   __restrict__ idx_j,
    const float* __restrict__ phi_r,
    const float* __restrict__ phi_chi,
    float* __restrict__ out,
    int n_pairs)
{
    const int e    = (blockIdx.x * blockDim.x + threadIdx.x) >> 5;
    const int lane = threadIdx.x & 31;
    if (e >= n_pairs) return;

    const int ni = idx_i[e];
    const int nj = idx_j[e];

    const Half4*  __restrict__ q4 = (const Half4*)(g_qh + (size_t)ni * NUM_FEAT);
    const Half4*  __restrict__ k4 = (const Half4*)(g_kh + (size_t)nj * NUM_FEAT);
    const float4* __restrict__ w4 = (const float4*)(w_ij + (size_t)e * NUM_FEAT);

    float a[NHEADS];
    #pragma unroll
    for (int hh = 0; hh < NHEADS; hh++) {
        const int idx = lane + hh * 32;
        const Half4  qh = q4[idx];
        const Half4  kh = k4[idx];
        const float4 wv = __ldcs(&w4[idx]);     // one-shot stream

        const float2 qa = __half22float2(qh.a);
        const float2 qb = __half22float2(qh.b);
        const float2 ka = __half22float2(kh.a);
        const float2 kb = __half22float2(kh.b);

        a[hh] = qa.x * wv.x * ka.x
              + qa.y * wv.y * ka.y
              + qb.x * wv.z * kb.x
              + qb.y * wv.w * kb.y;
    }

    #pragma unroll
    for (int off = 16; off > 0; off >>= 1) {
        #pragma unroll
        for (int hh = 0; hh < NHEADS; hh++)
            a[hh] += __shfl_xor_sync(0xFFFFFFFFu, a[hh], off);
    }

    const float cut = phi_r[e] + phi_chi[e];

    if (lane < SPH_DIM) {
        const float alpha = (lane < 3 ? a[0] : (lane < 8 ? a[1] : a[2])) * cut;
        atomicAdd(&out[(size_t)ni * SPH_DIM + lane],
                  alpha * __ldcs(&sph[(size_t)e * SPH_DIM + lane]));
    }
}

// ---------------------------------------------------------------------------
// Launch. Inputs (metadata order):
//  0: chi (unused)  1: sph_ij  2: x  3: w_ij  4: idx_i  5: phi_r_cut
//  6: phi_chi_cut   7: idx_j   8: Wq 9: Wk
// ---------------------------------------------------------------------------
extern "C" void kernel_launch(void* const* d_in, const int* in_sizes, int n_in,
                              void* d_out, int out_size)
{
    const float* sph     = (const float*)d_in[1];
    const float* x       = (const float*)d_in[2];
    const float* w_ij    = (const float*)d_in[3];
    const int*   idx_i   = (const int*)  d_in[4];
    const float* phi_r   = (const float*)d_in[5];
    const float* phi_chi = (const float*)d_in[6];
    const int*   idx_j   = (const int*)  d_in[7];
    const float* Wq      = (const float*)d_in[8];
    const float* Wk      = (const float*)d_in[9];
    float* out = (float*)d_out;

    const int n_nodes = in_sizes[2] / NUM_FEAT;
    const int n_pairs = in_sizes[4];

    // 1) projections (+ output zero-init inside)
    dim3 pgrid((n_nodes + 127) / 128, NHEADS, 2);
    proj_kernel<<<pgrid, 256>>>(x, Wq, Wk, out, out_size, n_nodes);

    // 2) edge attention + scatter
    const int warps_per_block = 256 / 32;
    const int eblocks = (n_pairs + warps_per_block - 1) / warps_per_block;
    edge_kernel<<<eblocks, 256>>>(w_ij, sph, idx_i, idx_j, phi_r, phi_chi,
                                  out, n_pairs);
}

// round 4
// speedup vs baseline: 2.3029x; 1.3568x over previous
#include <cuda_runtime.h>
#include <cuda_fp16.h>
#include <cstdint>

#define N_NODES_MAX   10000
#define NUM_FEAT      384
#define F_HEAD        128
#define NHEADS        3
#define SPH_DIM       15
#define INV_SQRT_FH   0.08838834764831845f   // 1/sqrt(128)

// Scratch: projected q/k in fp16 (device globals: no allocation allowed)
__device__ __half g_qh[N_NODES_MAX * NUM_FEAT];
__device__ __half g_kh[N_NODES_MAX * NUM_FEAT];

struct __align__(8) Half4 { __half2 a, b; };

// ---------------------------------------------------------------------------
// mma helpers
// ---------------------------------------------------------------------------
__device__ __forceinline__ uint32_t smem_u32(const void* p) {
    return static_cast<uint32_t>(__cvta_generic_to_shared(p));
}
__device__ __forceinline__ void ldsm_x4(uint32_t addr, uint32_t& r0, uint32_t& r1,
                                        uint32_t& r2, uint32_t& r3) {
    asm volatile("ldmatrix.sync.aligned.m8n8.x4.shared.b16 {%0,%1,%2,%3}, [%4];"
                 : "=r"(r0), "=r"(r1), "=r"(r2), "=r"(r3) : "r"(addr));
}
__device__ __forceinline__ void mma16816(float* c, const uint32_t* a,
                                         const uint32_t* b) {
    asm volatile(
        "mma.sync.aligned.m16n8k16.row.col.f32.f16.f16.f32 "
        "{%0,%1,%2,%3}, {%4,%5,%6,%7}, {%8,%9}, {%0,%1,%2,%3};"
        : "+f"(c[0]), "+f"(c[1]), "+f"(c[2]), "+f"(c[3])
        : "r"(a[0]), "r"(a[1]), "r"(a[2]), "r"(a[3]), "r"(b[0]), "r"(b[1]));
}

// ---------------------------------------------------------------------------
// Projection via fp16 tensor cores (fp32 accumulate):
//   q[n,h,g] = (1/sqrt128) * sum_f x[n,h*128+f] * Wq[h,g,f]
//   k[n,h,g] =               sum_f x[n,h*128+f] * Wk[h,g,f]
// C-tile 128x128 per block; 8 warps as 4(m) x 2(n), warp tile 32x64.
// K staged in 4 chunks of 32 (fp32 -> fp16 convert during staging).
// ldmatrix row stride = 40 halfs (80B) -> conflict-free.
// Also zero-inits `out` (blocks y==0,z==0).
// ---------------------------------------------------------------------------
__global__ __launch_bounds__(256, 2) void proj_kernel(
    const float* __restrict__ x,
    const float* __restrict__ Wq,
    const float* __restrict__ Wk,
    float* __restrict__ out, int out_n,
    int n_nodes)
{
    if (blockIdx.y == 0 && blockIdx.z == 0) {
        for (int i = blockIdx.x * 256 + threadIdx.x; i < out_n; i += gridDim.x * 256)
            out[i] = 0.0f;
    }

    const int h    = blockIdx.y;
    const int row0 = blockIdx.x * 128;
    const bool is_k = (blockIdx.z != 0);
    const float* __restrict__ W = (is_k ? Wk : Wq) + h * F_HEAD * F_HEAD;
    __half* __restrict__ o_base = is_k ? g_kh : g_qh;
    const float scale = is_k ? 1.0f : INV_SQRT_FH;

    __shared__ __half Xs[128][40];   // [row][k-chunk 32 + pad 8]
    __shared__ __half Ws[128][40];   // [g]  [k-chunk 32 + pad 8]

    const int tid  = threadIdx.x;
    const int warp = tid >> 5;
    const int lane = tid & 31;
    const int wm   = (warp & 3) * 32;   // warp row offset in C-tile
    const int wn   = (warp >> 2) * 64;  // warp col offset in C-tile

    // ldmatrix addresses (tiles restaged at same smem location each chunk)
    uint32_t a_addr[2][2];   // [mi][ki]
    #pragma unroll
    for (int mi = 0; mi < 2; mi++)
        #pragma unroll
        for (int ki = 0; ki < 2; ki++)
            a_addr[mi][ki] = smem_u32(
                &Xs[wm + mi * 16 + (lane & 15)][ki * 16 + (lane >> 4) * 8]);

    uint32_t b_addr[4][2];   // [nb][ki]; nb covers n-blocks 2nb, 2nb+1
    {
        const int nrow = (lane & 7) + ((lane >> 4) << 3);
        const int ksel = ((lane >> 3) & 1) * 8;
        #pragma unroll
        for (int nb = 0; nb < 4; nb++)
            #pragma unroll
            for (int ki = 0; ki < 2; ki++)
                b_addr[nb][ki] = smem_u32(
                    &Ws[wn + nb * 16 + nrow][ki * 16 + ksel]);
    }

    float acc[2][8][4];
    #pragma unroll
    for (int mi = 0; mi < 2; mi++)
        #pragma unroll
        for (int ni = 0; ni < 8; ni++)
            #pragma unroll
            for (int c = 0; c < 4; c++) acc[mi][ni][c] = 0.0f;

    for (int k0 = 0; k0 < F_HEAD; k0 += 32) {
        // ---- stage X and W chunks (fp32 -> fp16) ----
        #pragma unroll
        for (int t = tid; t < 128 * 16; t += 256) {
            const int r  = t >> 4;          // row / g
            const int c2 = t & 15;          // half2 column
            float2 xv = make_float2(0.f, 0.f);
            const int row = row0 + r;
            if (row < n_nodes)
                xv = *(const float2*)&x[(size_t)row * NUM_FEAT + h * F_HEAD + k0 + c2 * 2];
            *(__half2*)&Xs[r][c2 * 2] = __floats2half2_rn(xv.x, xv.y);

            const float2 wv = *(const float2*)&W[(size_t)r * F_HEAD + k0 + c2 * 2];
            *(__half2*)&Ws[r][c2 * 2] = __floats2half2_rn(wv.x, wv.y);
        }
        __syncthreads();

        // ---- ldmatrix + mma ----
        #pragma unroll
        for (int ki = 0; ki < 2; ki++) {
            uint32_t af[2][4];
            #pragma unroll
            for (int mi = 0; mi < 2; mi++)
                ldsm_x4(a_addr[mi][ki], af[mi][0], af[mi][1], af[mi][2], af[mi][3]);

            uint32_t bf[8][2];
            #pragma unroll
            for (int nb = 0; nb < 4; nb++) {
                uint32_t r0, r1, r2, r3;
                ldsm_x4(b_addr[nb][ki], r0, r1, r2, r3);
                bf[nb * 2 + 0][0] = r0;  bf[nb * 2 + 0][1] = r1;
                bf[nb * 2 + 1][0] = r2;  bf[nb * 2 + 1][1] = r3;
            }

            #pragma unroll
            for (int mi = 0; mi < 2; mi++)
                #pragma unroll
                for (int ni = 0; ni < 8; ni++)
                    mma16816(acc[mi][ni], af[mi], bf[ni]);
        }
        __syncthreads();
    }

    // ---- epilogue: scale + fp16 store ----
    #pragma unroll
    for (int mi = 0; mi < 2; mi++) {
        const int ra = row0 + wm + mi * 16 + (lane >> 2);
        const int rb = ra + 8;
        #pragma unroll
        for (int ni = 0; ni < 8; ni++) {
            const int col = h * F_HEAD + wn + ni * 8 + (lane & 3) * 2;
            if (ra < n_nodes)
                *(__half2*)(o_base + (size_t)ra * NUM_FEAT + col) =
                    __floats2half2_rn(acc[mi][ni][0] * scale, acc[mi][ni][1] * scale);
            if (rb < n_nodes)
                *(__half2*)(o_base + (size_t)rb * NUM_FEAT + col) =
                    __floats2half2_rn(acc[mi][ni][2] * scale, acc[mi][ni][3] * scale);
        }
    }
}

// ---------------------------------------------------------------------------
// Edge kernel: one warp per TWO edges (doubles MLP on the DRAM stream).
//   alpha_h = dot(q[i,h,:], w[e,h,:] * k[j,h,:])        (q pre-scaled)
//   alpha_h *= (phi_r[e] + phi_chi[e])
//   out[i, s] += alpha_{head(s)} * sph[e, s]            (atomic)
// ---------------------------------------------------------------------------
__global__ __launch_bounds__(256) void edge_kernel(
    const float* __restrict__ w_ij,
    const float* __restrict__ sph,
    const int*   __restrict__ idx_i,
    const int*   __restrict__ idx_j,
    const float* __restrict__ phi_r,
    const float* __restrict__ phi_chi,
    float* __restrict__ out,
    int n_pairs)
{
    const int gw   = (blockIdx.x * blockDim.x + threadIdx.x) >> 5;
    const int lane = threadIdx.x & 31;
    const int e0   = gw * 2;
    if (e0 >= n_pairs) return;
    const bool has2 = (e0 + 1 < n_pairs);
    const int e1 = has2 ? e0 + 1 : e0;

    const int ni0 = idx_i[e0], nj0 = idx_j[e0];
    const int ni1 = idx_i[e1], nj1 = idx_j[e1];

    const Half4*  __restrict__ q0 = (const Half4*)(g_qh + (size_t)ni0 * NUM_FEAT);
    const Half4*  __restrict__ k0 = (const Half4*)(g_kh + (size_t)nj0 * NUM_FEAT);
    const float4* __restrict__ w0 = (const float4*)(w_ij + (size_t)e0 * NUM_FEAT);
    const Half4*  __restrict__ q1 = (const Half4*)(g_qh + (size_t)ni1 * NUM_FEAT);
    const Half4*  __restrict__ k1 = (const Half4*)(g_kh + (size_t)nj1 * NUM_FEAT);
    const float4* __restrict__ w1 = (const float4*)(w_ij + (size_t)e1 * NUM_FEAT);

    float a0[NHEADS], a1[NHEADS];
    #pragma unroll
    for (int hh = 0; hh < NHEADS; hh++) {
        const int idx = lane + hh * 32;
        // issue all loads for both edges up front (independent)
        const float4 wv0 = __ldcs(&w0[idx]);
        const float4 wv1 = __ldcs(&w1[idx]);
        const Half4  qh0 = q0[idx];
        const Half4  kh0 = k0[idx];
        const Half4  qh1 = q1[idx];
        const Half4  kh1 = k1[idx];

        {
            const float2 qa = __half22float2(qh0.a), qb = __half22float2(qh0.b);
            const float2 ka = __half22float2(kh0.a), kb = __half22float2(kh0.b);
            a0[hh] = qa.x * wv0.x * ka.x + qa.y * wv0.y * ka.y
                   + qb.x * wv0.z * kb.x + qb.y * wv0.w * kb.y;
        }
        {
            const float2 qa = __half22float2(qh1.a), qb = __half22float2(qh1.b);
            const float2 ka = __half22float2(kh1.a), kb = __half22float2(kh1.b);
            a1[hh] = qa.x * wv1.x * ka.x + qa.y * wv1.y * ka.y
                   + qb.x * wv1.z * kb.x + qb.y * wv1.w * kb.y;
        }
    }

    #pragma unroll
    for (int off = 16; off > 0; off >>= 1) {
        #pragma unroll
        for (int hh = 0; hh < NHEADS; hh++) {
            a0[hh] += __shfl_xor_sync(0xFFFFFFFFu, a0[hh], off);
            a1[hh] += __shfl_xor_sync(0xFFFFFFFFu, a1[hh], off);
        }
    }

    const float cut0 = phi_r[e0] + phi_chi[e0];
    const float cut1 = phi_r[e1] + phi_chi[e1];

    if (lane < SPH_DIM) {
        const float al0 = (lane < 3 ? a0[0] : (lane < 8 ? a0[1] : a0[2])) * cut0;
        atomicAdd(&out[(size_t)ni0 * SPH_DIM + lane],
                  al0 * __ldcs(&sph[(size_t)e0 * SPH_DIM + lane]));
        if (has2) {
            const float al1 = (lane < 3 ? a1[0] : (lane < 8 ? a1[1] : a1[2])) * cut1;
            atomicAdd(&out[(size_t)ni1 * SPH_DIM + lane],
                      al1 * __ldcs(&sph[(size_t)e1 * SPH_DIM + lane]));
        }
    }
}

// ---------------------------------------------------------------------------
// Launch. Inputs (metadata order):
//  0: chi (unused)  1: sph_ij  2: x  3: w_ij  4: idx_i  5: phi_r_cut
//  6: phi_chi_cut   7: idx_j   8: Wq 9: Wk
// ---------------------------------------------------------------------------
extern "C" void kernel_launch(void* const* d_in, const int* in_sizes, int n_in,
                              void* d_out, int out_size)
{
    const float* sph     = (const float*)d_in[1];
    const float* x       = (const float*)d_in[2];
    const float* w_ij    = (const float*)d_in[3];
    const int*   idx_i   = (const int*)  d_in[4];
    const float* phi_r   = (const float*)d_in[5];
    const float* phi_chi = (const float*)d_in[6];
    const int*   idx_j   = (const int*)  d_in[7];
    const float* Wq      = (const float*)d_in[8];
    const float* Wk      = (const float*)d_in[9];
    float* out = (float*)d_out;

    const int n_nodes = in_sizes[2] / NUM_FEAT;
    const int n_pairs = in_sizes[4];

    dim3 pgrid((n_nodes + 127) / 128, NHEADS, 2);
    proj_kernel<<<pgrid, 256>>>(x, Wq, Wk, out, out_size, n_nodes);

    const int edges_per_block = (256 / 32) * 2;
    const int eblocks = (n_pairs + edges_per_block - 1) / edges_per_block;
    edge_kernel<<<eblocks, 256>>>(w_ij, sph, idx_i, idx_j, phi_r, phi_chi,
                                  out, n_pairs);
}